// round 3
// baseline (speedup 1.0000x reference)
#include <cuda_runtime.h>

#define BATCH 8
#define CH 64
#define NPTS 65536
#define RR 32
#define NVOX 32768  // 32^3

// ---------------- scratch (__device__ globals; no allocation allowed) ------
__device__ float d_mean[BATCH * 3];
__device__ float d_scale[BATCH];
__device__ float d_voxc[BATCH * 3 * NPTS];          // clipped voxel coords (for devox)
__device__ float d_cnt[BATCH * NVOX];               // per-voxel point counts
__device__ float d_grid0[(size_t)BATCH * NVOX * CH]; // NDHWC voxel grid (scatter sums -> avg)
__device__ float d_grid1[(size_t)BATCH * NVOX * CH]; // after conv1
__device__ float d_grid2[(size_t)BATCH * NVOX * CH]; // after conv2
__device__ float d_wT1[27 * 64 * 64];               // [tap][ic][oc], BN-scale folded
__device__ float d_wT2[27 * 64 * 64];
__device__ float d_biasE1[64];
__device__ float d_biasE2[64];

// ---------------- zero scratch each launch (graph replays!) ----------------
__global__ void zero_kernel() {
    size_t t = (size_t)blockIdx.x * 256 + threadIdx.x;
    const size_t g4 = (size_t)BATCH * NVOX * CH / 4;   // 4194304 float4s
    float4 z = make_float4(0.f, 0.f, 0.f, 0.f);
    if (t < g4) {
        reinterpret_cast<float4*>(d_grid0)[t] = z;
    } else {
        size_t u = t - g4;
        if (u < (size_t)BATCH * NVOX / 4) reinterpret_cast<float4*>(d_cnt)[u] = z;
    }
}

// ---------------- per-batch coords mean ------------------------------------
__global__ void mean_kernel(const float* __restrict__ coords) {
    int b = blockIdx.x, tid = threadIdx.x;
    const float* cb = coords + (size_t)b * 3 * NPTS;
    float s0 = 0.f, s1 = 0.f, s2 = 0.f;
    for (int n = tid; n < NPTS; n += 256) {
        s0 += cb[n];
        s1 += cb[NPTS + n];
        s2 += cb[2 * NPTS + n];
    }
    __shared__ float sh[3][256];
    sh[0][tid] = s0; sh[1][tid] = s1; sh[2][tid] = s2;
    __syncthreads();
    for (int off = 128; off > 0; off >>= 1) {
        if (tid < off) {
            sh[0][tid] += sh[0][tid + off];
            sh[1][tid] += sh[1][tid + off];
            sh[2][tid] += sh[2][tid + off];
        }
        __syncthreads();
    }
    if (tid == 0) {
        d_mean[b * 3 + 0] = sh[0][0] / (float)NPTS;
        d_mean[b * 3 + 1] = sh[1][0] / (float)NPTS;
        d_mean[b * 3 + 2] = sh[2][0] / (float)NPTS;
    }
}

// ---------------- per-batch max point radius -------------------------------
__global__ void scale_kernel(const float* __restrict__ coords) {
    int b = blockIdx.x, tid = threadIdx.x;
    const float* cb = coords + (size_t)b * 3 * NPTS;
    float m0 = d_mean[b * 3 + 0], m1 = d_mean[b * 3 + 1], m2 = d_mean[b * 3 + 2];
    float mx = 0.f;
    for (int n = tid; n < NPTS; n += 256) {
        float dx = cb[n] - m0;
        float dy = cb[NPTS + n] - m1;
        float dz = cb[2 * NPTS + n] - m2;
        mx = fmaxf(mx, dx * dx + dy * dy + dz * dz);
    }
    __shared__ float sh[256];
    sh[tid] = mx;
    __syncthreads();
    for (int off = 128; off > 0; off >>= 1) {
        if (tid < off) sh[tid] = fmaxf(sh[tid], sh[tid + off]);
        __syncthreads();
    }
    if (tid == 0) d_scale[b] = sqrtf(sh[0]);
}

// ---------------- weight transpose + BN fold -------------------------------
// wT[(tap*64+ic)*64+oc] = w[oc][ic][tap] * g[oc]/sqrt(v[oc]+eps)
// biasE[oc] = (b[oc]-m[oc])*g[oc]/sqrt(v[oc]+eps) + be[oc]
__global__ void prep_kernel(const float* __restrict__ w, const float* __restrict__ bias,
                            const float* __restrict__ g, const float* __restrict__ be,
                            const float* __restrict__ m, const float* __restrict__ v,
                            float* __restrict__ wT, float* __restrict__ biasE) {
    int i = blockIdx.x * 256 + threadIdx.x;
    if (i < 64) {
        float sc = g[i] * rsqrtf(v[i] + 1e-4f);
        biasE[i] = (bias[i] - m[i]) * sc + be[i];
    }
    if (i < 27 * 64 * 64) {
        int oc = i & 63;
        int ic = (i >> 6) & 63;
        int tap = i >> 12;
        float sc = g[oc] * rsqrtf(v[oc] + 1e-4f);
        wT[i] = w[(oc * 64 + ic) * 27 + tap] * sc;
    }
}

// ---------------- voxelize: normalize coords + scatter-add -----------------
__global__ void scatter_kernel(const float* __restrict__ coords,
                               const float* __restrict__ feats) {
    int t = blockIdx.x * 256 + threadIdx.x;       // t in [0, BATCH*NPTS)
    int b = t >> 16;
    int n = t & (NPTS - 1);
    const float* cb = coords + (size_t)b * 3 * NPTS;
    float m0 = d_mean[b * 3 + 0], m1 = d_mean[b * 3 + 1], m2 = d_mean[b * 3 + 2];
    float den = d_scale[b] * 2.0f;

    float vx = fminf(fmaxf(((cb[n]            - m0) / den + 0.5f) * 32.0f, 0.f), 31.f);
    float vy = fminf(fmaxf(((cb[NPTS + n]     - m1) / den + 0.5f) * 32.0f, 0.f), 31.f);
    float vz = fminf(fmaxf(((cb[2 * NPTS + n] - m2) / den + 0.5f) * 32.0f, 0.f), 31.f);

    float* vout = d_voxc + (size_t)b * 3 * NPTS;
    vout[n] = vx;
    vout[NPTS + n] = vy;
    vout[2 * NPTS + n] = vz;

    int ix = (int)rintf(vx);   // round-half-even, matches jnp.round
    int iy = (int)rintf(vy);
    int iz = (int)rintf(vz);
    int idx = (ix * 32 + iy) * 32 + iz;

    atomicAdd(&d_cnt[b * NVOX + idx], 1.0f);
    float* gb = &d_grid0[((size_t)b * NVOX + idx) * CH];
    const float* fb = feats + (size_t)b * CH * NPTS + n;
#pragma unroll 8
    for (int c = 0; c < CH; c++)
        atomicAdd(&gb[c], fb[(size_t)c * NPTS]);
}

// ---------------- divide sums by counts ------------------------------------
__global__ void avg_kernel() {
    int t = blockIdx.x * 256 + threadIdx.x;   // t in [0, BATCH*NVOX*16)
    int vox = t >> 4;
    int c4 = t & 15;
    float inv = 1.0f / fmaxf(d_cnt[vox], 1.0f);
    float4* p = reinterpret_cast<float4*>(&d_grid0[(size_t)vox * CH + c4 * 4]);
    float4 x = *p;
    x.x *= inv; x.y *= inv; x.z *= inv; x.w *= inv;
    *p = x;
}

// ---------------- 3x3x3 conv 64->64 + folded BN + LeakyReLU ----------------
// NDHWC. Block: 4x4x8 voxel tile, all 64 oc. 256 threads, each: 8 voxels x 4 oc.
#define TTX 4
#define TTY 4
#define TTZ 8
#define HVOX 360              // 6*6*10 halo voxels
#define INSTRIDE 68           // 64 ch padded for bank spread + float4 alignment
#define IN_SH_FLOATS (HVOX * INSTRIDE)   // 24480
#define W_SH_FLOATS (64 * 64)            // 4096
#define CONV_SMEM ((IN_SH_FLOATS + W_SH_FLOATS) * 4)

__global__ void __launch_bounds__(256) conv_kernel(const float* __restrict__ gin,
                                                   float* __restrict__ gout,
                                                   const float* __restrict__ wT,
                                                   const float* __restrict__ biasE) {
    extern __shared__ float sh[];
    float* in_sh = sh;
    float* w_sh = sh + IN_SH_FLOATS;
    int tid = threadIdx.x;
    int bx = blockIdx.x;
    int b = bx >> 8;              // 256 tiles per batch
    int tile = bx & 255;
    int tz = tile & 3;
    int ty = (tile >> 2) & 7;
    int txi = tile >> 5;
    int x0 = txi * TTX, y0 = ty * TTY, z0 = tz * TTZ;

    // load 6x6x10 halo tile, zero-padded
    for (int s = tid; s < HVOX * 16; s += 256) {
        int vox = s >> 4, c4 = s & 15;
        int hz = vox % 10;
        int tmp = vox / 10;
        int hy = tmp % 6;
        int hx = tmp / 6;
        int gx = x0 + hx - 1, gy = y0 + hy - 1, gz = z0 + hz - 1;
        float4 val = make_float4(0.f, 0.f, 0.f, 0.f);
        if ((unsigned)gx < 32u && (unsigned)gy < 32u && (unsigned)gz < 32u)
            val = *reinterpret_cast<const float4*>(
                &gin[((((size_t)b * 32 + gx) * 32 + gy) * 32 + gz) * CH + c4 * 4]);
        *reinterpret_cast<float4*>(&in_sh[vox * INSTRIDE + c4 * 4]) = val;
    }

    int vg = tid & 15, og = tid >> 4;
    int lx = vg >> 2, ly = vg & 3;
    int oc0 = og * 4;

    float acc[8][4];
#pragma unroll
    for (int v = 0; v < 8; v++)
#pragma unroll
        for (int j = 0; j < 4; j++) acc[v][j] = 0.f;

    for (int tap = 0; tap < 27; tap++) {
        __syncthreads();   // (first iter: also fences halo load; later: protects w_sh)
        {
            const float4* wsrc = reinterpret_cast<const float4*>(wT + tap * 4096);
            float4* wdst = reinterpret_cast<float4*>(w_sh);
            for (int i = tid; i < 1024; i += 256) wdst[i] = wsrc[i];
        }
        __syncthreads();
        int dxi = tap / 9;
        int rr = tap - dxi * 9;
        int dyi = rr / 3;
        int dzi = rr - dyi * 3;
        const float* ip = &in_sh[(((lx + dxi) * 6 + (ly + dyi)) * 10 + dzi) * INSTRIDE];
#pragma unroll 4
        for (int ic4 = 0; ic4 < 16; ic4++) {
            float4 a[8];
#pragma unroll
            for (int v = 0; v < 8; v++)
                a[v] = *reinterpret_cast<const float4*>(&ip[v * INSTRIDE + ic4 * 4]);
#pragma unroll
            for (int j = 0; j < 4; j++) {
                float4 wv = *reinterpret_cast<const float4*>(
                    &w_sh[((ic4 * 4 + j) << 6) + oc0]);
#pragma unroll
                for (int v = 0; v < 8; v++) {
                    float av = (j == 0) ? a[v].x : (j == 1) ? a[v].y
                             : (j == 2) ? a[v].z : a[v].w;
                    acc[v][0] += av * wv.x;
                    acc[v][1] += av * wv.y;
                    acc[v][2] += av * wv.z;
                    acc[v][3] += av * wv.w;
                }
            }
        }
    }

    float bb0 = biasE[oc0], bb1 = biasE[oc0 + 1], bb2 = biasE[oc0 + 2], bb3 = biasE[oc0 + 3];
#pragma unroll
    for (int v = 0; v < 8; v++) {
        float y0v = acc[v][0] + bb0;
        float y1v = acc[v][1] + bb1;
        float y2v = acc[v][2] + bb2;
        float y3v = acc[v][3] + bb3;
        y0v = (y0v >= 0.f) ? y0v : 0.1f * y0v;
        y1v = (y1v >= 0.f) ? y1v : 0.1f * y1v;
        y2v = (y2v >= 0.f) ? y2v : 0.1f * y2v;
        y3v = (y3v >= 0.f) ? y3v : 0.1f * y3v;
        size_t o = ((((size_t)b * 32 + (x0 + lx)) * 32 + (y0 + ly)) * 32 + (z0 + v)) * CH + oc0;
        *reinterpret_cast<float4*>(&gout[o]) = make_float4(y0v, y1v, y2v, y3v);
    }
}

// ---------------- trilinear devoxelize -> point features -------------------
__global__ void devox_kernel(float* __restrict__ out, const float* __restrict__ grid) {
    int n = blockIdx.x * 256 + threadIdx.x;
    int cg = blockIdx.y;     // 16 channel-groups of 4
    int b = blockIdx.z;
    const float* vc = d_voxc + (size_t)b * 3 * NPTS;
    float cx = vc[n], cy = vc[NPTS + n], cz = vc[2 * NPTS + n];
    int ix0 = (int)floorf(cx), iy0 = (int)floorf(cy), iz0 = (int)floorf(cz);
    float fx = cx - (float)ix0, fy = cy - (float)iy0, fz = cz - (float)iz0;
    int ix1 = min(ix0 + 1, 31), iy1 = min(iy0 + 1, 31), iz1 = min(iz0 + 1, 31);
    float gx0 = 1.f - fx, gy0 = 1.f - fy, gz0 = 1.f - fz;

    const float* g = grid + ((size_t)b * NVOX) * CH + cg * 4;
    float4 acc = make_float4(0.f, 0.f, 0.f, 0.f);

#define CORNER(XI, YI, ZI, W)                                                        \
    {                                                                                \
        float4 cv = *reinterpret_cast<const float4*>(                                \
            &g[(size_t)(((XI) * 32 + (YI)) * 32 + (ZI)) * CH]);                      \
        float ww = (W);                                                              \
        acc.x += ww * cv.x; acc.y += ww * cv.y; acc.z += ww * cv.z; acc.w += ww * cv.w; \
    }
    CORNER(ix0, iy0, iz0, gx0 * gy0 * gz0)
    CORNER(ix0, iy0, iz1, gx0 * gy0 * fz)
    CORNER(ix0, iy1, iz0, gx0 * fy * gz0)
    CORNER(ix0, iy1, iz1, gx0 * fy * fz)
    CORNER(ix1, iy0, iz0, fx * gy0 * gz0)
    CORNER(ix1, iy0, iz1, fx * gy0 * fz)
    CORNER(ix1, iy1, iz0, fx * fy * gz0)
    CORNER(ix1, iy1, iz1, fx * fy * fz)
#undef CORNER

    size_t ob = ((size_t)b * CH + cg * 4) * NPTS + n;
    out[ob] = acc.x;
    out[ob + NPTS] = acc.y;
    out[ob + 2 * (size_t)NPTS] = acc.z;
    out[ob + 3 * (size_t)NPTS] = acc.w;
}

// ---------------- echo coords into output tail -----------------------------
__global__ void copy_coords_kernel(float* __restrict__ out, const float* __restrict__ coords) {
    int t = blockIdx.x * 256 + threadIdx.x;   // t < BATCH*3*NPTS/4 = 393216
    reinterpret_cast<float4*>(out)[t] = reinterpret_cast<const float4*>(coords)[t];
}

// ---------------- launch ----------------------------------------------------
extern "C" void kernel_launch(void* const* d_in, const int* in_sizes, int n_in,
                              void* d_out, int out_size) {
    (void)in_sizes; (void)n_in; (void)out_size;
    const float* feats  = (const float*)d_in[0];
    const float* coords = (const float*)d_in[1];
    const float* w1  = (const float*)d_in[2];
    const float* b1  = (const float*)d_in[3];
    const float* g1  = (const float*)d_in[4];
    const float* be1 = (const float*)d_in[5];
    const float* m1  = (const float*)d_in[6];
    const float* v1  = (const float*)d_in[7];
    const float* w2  = (const float*)d_in[8];
    const float* b2  = (const float*)d_in[9];
    const float* g2  = (const float*)d_in[10];
    const float* be2 = (const float*)d_in[11];
    const float* m2  = (const float*)d_in[12];
    const float* v2  = (const float*)d_in[13];
    float* out = (float*)d_out;

    float *p_g0, *p_g1, *p_g2, *p_wT1, *p_wT2, *p_be1, *p_be2;
    cudaGetSymbolAddress((void**)&p_g0, d_grid0);
    cudaGetSymbolAddress((void**)&p_g1, d_grid1);
    cudaGetSymbolAddress((void**)&p_g2, d_grid2);
    cudaGetSymbolAddress((void**)&p_wT1, d_wT1);
    cudaGetSymbolAddress((void**)&p_wT2, d_wT2);
    cudaGetSymbolAddress((void**)&p_be1, d_biasE1);
    cudaGetSymbolAddress((void**)&p_be2, d_biasE2);

    cudaFuncSetAttribute(conv_kernel, cudaFuncAttributeMaxDynamicSharedMemorySize, CONV_SMEM);

    zero_kernel<<<16640, 256>>>();
    mean_kernel<<<BATCH, 256>>>(coords);
    scale_kernel<<<BATCH, 256>>>(coords);
    prep_kernel<<<(27 * 64 * 64 + 255) / 256, 256>>>(w1, b1, g1, be1, m1, v1, p_wT1, p_be1);
    prep_kernel<<<(27 * 64 * 64 + 255) / 256, 256>>>(w2, b2, g2, be2, m2, v2, p_wT2, p_be2);
    scatter_kernel<<<(BATCH * NPTS) / 256, 256>>>(coords, feats);
    avg_kernel<<<(BATCH * NVOX * 16) / 256, 256>>>();
    conv_kernel<<<BATCH * 256, 256, CONV_SMEM>>>(p_g0, p_g1, p_wT1, p_be1);
    conv_kernel<<<BATCH * 256, 256, CONV_SMEM>>>(p_g1, p_g2, p_wT2, p_be2);
    devox_kernel<<<dim3(NPTS / 256, 16, BATCH), 256>>>(out, p_g2);
    copy_coords_kernel<<<(BATCH * 3 * NPTS / 4) / 256, 256>>>(
        out + (size_t)BATCH * CH * NPTS, coords);
}